// round 13
// baseline (speedup 1.0000x reference)
#include <cuda_runtime.h>
#include <cuda_fp16.h>
#include <math.h>
#include <stdint.h>

#define NN 50000
#define FF 128
#define HH 256
#define CC 512
#define EE 800000

// ---------------- scratch (device globals; no allocation allowed) -------------
__device__ int      g_cnt[NN];
__device__ int      g_rowstart[NN];
__device__ int      g_fill[NN];
__device__ int      g_incl[NN];
__device__ int      g_bsum[64];
__device__ int      g_csr[EE];
__device__ float    g_inv[NN];
__device__ float    g_hs[NN];
__device__ float    g_invs[NN];
__device__ float    g_ivh[NN];
__device__ int      g_cluster[NN];
__device__ unsigned long long g_ckey[CC];  // (fkey(score)<<32)|(0x7FFFFFFF-i)
__device__ int      g_nonempty[CC];
__device__ float    g_h[(size_t)NN * HH];    // fp32 hidden activations
__device__ float    g_h3[(size_t)NN * CC];   // layer-3 pre-softmax
__device__ __half   g_Ph[(size_t)NN * HH];   // prop output, fp16 hi
__device__ __half   g_Pl[(size_t)NN * HH];   // prop output, fp16 lo
__device__ __half   g_Wth[(size_t)CC * HH];  // Wt split hi [N][K]
__device__ __half   g_Wtl[(size_t)CC * HH];  // Wt split lo [N][K]

// monotonic float<->uint key for atomicMax on floats
__device__ __forceinline__ unsigned fkey(float f) {
    unsigned u = __float_as_uint(f);
    return (u & 0x80000000u) ? ~u : (u | 0x80000000u);
}
__device__ __forceinline__ float fdec(unsigned k) {
    return (k & 0x80000000u) ? __uint_as_float(k ^ 0x80000000u)
                             : __uint_as_float(~k);
}

__device__ __forceinline__ void f16_split(float v, __half& hi, __half& lo) {
    hi = __float2half_rn(v);
    lo = __float2half_rn(v - __half2float(hi));
}

// ---------------- setup kernels ----------------------------------------------
__global__ void k_init() {
    int i = blockIdx.x * blockDim.x + threadIdx.x;
    if (i < NN) g_cnt[i] = 0;
    if (i < CC) { g_ckey[i] = 0ull; g_nonempty[i] = 0; }
}

__global__ void k_count(const int* __restrict__ dst) {
    int e = blockIdx.x * blockDim.x + threadIdx.x;
    if (e < EE) atomicAdd(&g_cnt[dst[e]], 1);
}

__global__ void k_scan1() {
    __shared__ int s[1024];
    int g = blockIdx.x * 1024 + threadIdx.x;
    int v = (g < NN) ? g_cnt[g] : 0;
    s[threadIdx.x] = v;
    __syncthreads();
    for (int off = 1; off < 1024; off <<= 1) {
        int t = (threadIdx.x >= off) ? s[threadIdx.x - off] : 0;
        __syncthreads();
        s[threadIdx.x] += t;
        __syncthreads();
    }
    if (g < NN) g_incl[g] = s[threadIdx.x];
    if (threadIdx.x == 1023) g_bsum[blockIdx.x] = s[1023];
}

__global__ void k_scan2(int nb) {
    if (threadIdx.x == 0 && blockIdx.x == 0) {
        int a = 0;
        for (int i = 0; i < nb; i++) { int t = g_bsum[i]; g_bsum[i] = a; a += t; }
    }
}

__global__ void k_scan3() {
    int g = blockIdx.x * blockDim.x + threadIdx.x;
    if (g < NN) {
        int rs = g_incl[g] + g_bsum[g >> 10] - g_cnt[g];
        g_rowstart[g] = rs;
        g_fill[g] = rs;
        g_inv[g] = rsqrtf((float)g_cnt[g] + 1.0f);
    }
}

__global__ void k_scatter(const int* __restrict__ src, const int* __restrict__ dst) {
    int e = blockIdx.x * blockDim.x + threadIdx.x;
    if (e < EE) {
        int p = atomicAdd(&g_fill[dst[e]], 1);
        g_csr[p] = src[e];
    }
}

// ------- GCN propagation, warp-per-node, float4; writes SPLIT fp16 output -----
template <int F>
__global__ __launch_bounds__(256) void k_prop(const float* __restrict__ X,
                                              __half* __restrict__ Yh,
                                              __half* __restrict__ Yl) {
    constexpr int V = F / 128;
    int w = blockIdx.x * (blockDim.x >> 5) + (threadIdx.x >> 5);
    int lane = threadIdx.x & 31;
    if (w >= NN) return;
    float invi = g_inv[w];
    const float4* Xw = (const float4*)(X + (size_t)w * F);
    float4 acc[V];
#pragma unroll
    for (int v = 0; v < V; v++) {
        float4 t = Xw[lane + v * 32];
        acc[v] = make_float4(invi * t.x, invi * t.y, invi * t.z, invi * t.w);
    }
    int beg = g_rowstart[w];
    int end = beg + g_cnt[w];
    int j = beg;
    for (; j + 4 <= end; j += 4) {
        int s0 = g_csr[j], s1 = g_csr[j + 1], s2 = g_csr[j + 2], s3 = g_csr[j + 3];
        float w0 = g_inv[s0], w1 = g_inv[s1], w2 = g_inv[s2], w3 = g_inv[s3];
        const float4* r0 = (const float4*)(X + (size_t)s0 * F);
        const float4* r1 = (const float4*)(X + (size_t)s1 * F);
        const float4* r2 = (const float4*)(X + (size_t)s2 * F);
        const float4* r3 = (const float4*)(X + (size_t)s3 * F);
#pragma unroll
        for (int v = 0; v < V; v++) {
            float4 t0 = r0[lane + v * 32];
            float4 t1 = r1[lane + v * 32];
            float4 t2 = r2[lane + v * 32];
            float4 t3 = r3[lane + v * 32];
            acc[v].x += w0 * t0.x + w1 * t1.x + w2 * t2.x + w3 * t3.x;
            acc[v].y += w0 * t0.y + w1 * t1.y + w2 * t2.y + w3 * t3.y;
            acc[v].z += w0 * t0.z + w1 * t1.z + w2 * t2.z + w3 * t3.z;
            acc[v].w += w0 * t0.w + w1 * t1.w + w2 * t2.w + w3 * t3.w;
        }
    }
    for (; j < end; j++) {
        int s0 = g_csr[j];
        float w0 = g_inv[s0];
        const float4* r0 = (const float4*)(X + (size_t)s0 * F);
#pragma unroll
        for (int v = 0; v < V; v++) {
            float4 t0 = r0[lane + v * 32];
            acc[v].x += w0 * t0.x; acc[v].y += w0 * t0.y;
            acc[v].z += w0 * t0.z; acc[v].w += w0 * t0.w;
        }
    }
#pragma unroll
    for (int v = 0; v < V; v++) {
        __half h0, l0, h1, l1, h2, l2, h3, l3;
        f16_split(invi * acc[v].x, h0, l0);
        f16_split(invi * acc[v].y, h1, l1);
        f16_split(invi * acc[v].z, h2, l2);
        f16_split(invi * acc[v].w, h3, l3);
        size_t o = (size_t)w * F + (lane + v * 32) * 4;
        __half2* ph = (__half2*)(Yh + o);
        ph[0] = __halves2half2(h0, h1);
        ph[1] = __halves2half2(h2, h3);
        __half2* pl = (__half2*)(Yl + o);
        pl[0] = __halves2half2(l0, l1);
        pl[1] = __halves2half2(l2, l3);
    }
}

// -------- weight transpose + split: W[K,N] -> Wth/Wtl[N,K] fp16 ----------------
__global__ void k_transW(const float* __restrict__ W, __half* __restrict__ Wth,
                         __half* __restrict__ Wtl, int K, int N) {
    __shared__ float tile[32][33];
    int n0 = blockIdx.x * 32, k0 = blockIdx.y * 32;
    int tx = threadIdx.x, ty = threadIdx.y;  // 32 x 8
#pragma unroll
    for (int i = 0; i < 4; i++)
        tile[ty + i * 8][tx] = W[(size_t)(k0 + ty + i * 8) * N + n0 + tx];
    __syncthreads();
#pragma unroll
    for (int i = 0; i < 4; i++) {
        float v = tile[tx][ty + i * 8];
        __half h, l;
        f16_split(v, h, l);
        size_t o = (size_t)(n0 + ty + i * 8) * K + k0 + tx;
        Wth[o] = h;
        Wtl[o] = l;
    }
}

// ---------------- fp16x3 tensor-core GEMM, cp.async 3-stage pipeline -----------
// C[M,N] = A[M,K] @ Bt[N,K]^T + bias, optional relu. Operands pre-split fp16.
#define GBM 128
#define GBN 128
#define GBK 32
#define HSTR 40                      // halves per smem row (32 + 8 pad)
#define HTILE (128 * HSTR)           // halves per tile
#define STG_H (4 * HTILE)            // halves per stage: Ah, Al, Bh, Bl
#define NSTAGE 3
#define GEMM_SMEM_BYTES (NSTAGE * STG_H * 2)   // 122880

__device__ __forceinline__ void cp16(uint32_t dst, const void* src, bool valid) {
    int sz = valid ? 16 : 0;
    asm volatile("cp.async.cg.shared.global [%0], [%1], 16, %2;\n"
                 :: "r"(dst), "l"(src), "r"(sz));
}
__device__ __forceinline__ void cp_commit() {
    asm volatile("cp.async.commit_group;\n" ::: "memory");
}
template <int N>
__device__ __forceinline__ void cp_wait() {
    asm volatile("cp.async.wait_group %0;\n" :: "n"(N) : "memory");
}

__device__ __forceinline__ void mma_f16(float c[4], uint32_t a0, uint32_t a1,
                                        uint32_t a2, uint32_t a3,
                                        uint32_t b0, uint32_t b1) {
    asm volatile(
        "mma.sync.aligned.m16n8k16.row.col.f32.f16.f16.f32 "
        "{%0,%1,%2,%3}, {%4,%5,%6,%7}, {%8,%9}, {%0,%1,%2,%3};"
        : "+f"(c[0]), "+f"(c[1]), "+f"(c[2]), "+f"(c[3])
        : "r"(a0), "r"(a1), "r"(a2), "r"(a3), "r"(b0), "r"(b1));
}

__global__ __launch_bounds__(512, 1) void k_gemm_fp16(
    const __half* __restrict__ Ahi, const __half* __restrict__ Alo,
    const __half* __restrict__ Bhi, const __half* __restrict__ Blo,
    const float* __restrict__ bias, float* __restrict__ C,
    int M, int N, int K, int doRelu) {
    extern __shared__ __half hsm[];
    uint32_t smem_base;
    asm("{ .reg .u64 t; cvta.to.shared.u64 t, %1; cvt.u32.u64 %0, t; }"
        : "=r"(smem_base) : "l"(hsm));

    int tid = threadIdx.x;
    int warp = tid >> 5;
    int lane = tid & 31;
    int gid = lane >> 2;
    int tig = lane & 3;
    int wm = warp >> 2;
    int wn = warp & 3;

    int m0 = blockIdx.y * GBM;
    int n0 = blockIdx.x * GBN;

    float acc[2][4][4];
#pragma unroll
    for (int mt = 0; mt < 2; mt++)
#pragma unroll
        for (int nt = 0; nt < 4; nt++)
#pragma unroll
            for (int r = 0; r < 4; r++) acc[mt][nt][r] = 0.0f;

    // cp.async mapping: row = tid>>2 (0..127), chunk = tid&3 (16B each, 64B/row)
    int c_row = tid >> 2;
    int c_chk = tid & 3;
    bool a_ok = (m0 + c_row) < M;

    auto loadStage = [&](int t, int stage) {
        int k0 = t * GBK;
        uint32_t sb = smem_base + (uint32_t)stage * (STG_H * 2)
                    + (uint32_t)(c_row * HSTR * 2 + c_chk * 16);
        size_t ao = (size_t)(m0 + c_row) * K + k0 + c_chk * 8;
        size_t bo = (size_t)(n0 + c_row) * K + k0 + c_chk * 8;
        cp16(sb,                 Ahi + ao, a_ok);
        cp16(sb + HTILE * 2,     Alo + ao, a_ok);
        cp16(sb + 2 * HTILE * 2, Bhi + bo, true);
        cp16(sb + 3 * HTILE * 2, Blo + bo, true);
    };

    auto compute = [&](int stage) {
        const __half* Ah = hsm + stage * STG_H;
        const __half* Al = Ah + HTILE;
        const __half* Bh = Al + HTILE;
        const __half* Bl = Bh + HTILE;
#pragma unroll
        for (int ks = 0; ks < GBK / 16; ks++) {
            int kc = ks * 16 + 2 * tig;
            uint32_t ah[2][4], al[2][4];
#pragma unroll
            for (int mt = 0; mt < 2; mt++) {
                int rm = wm * 32 + mt * 16;
                ah[mt][0] = *(const uint32_t*)&Ah[(rm + gid) * HSTR + kc];
                ah[mt][1] = *(const uint32_t*)&Ah[(rm + gid + 8) * HSTR + kc];
                ah[mt][2] = *(const uint32_t*)&Ah[(rm + gid) * HSTR + kc + 8];
                ah[mt][3] = *(const uint32_t*)&Ah[(rm + gid + 8) * HSTR + kc + 8];
                al[mt][0] = *(const uint32_t*)&Al[(rm + gid) * HSTR + kc];
                al[mt][1] = *(const uint32_t*)&Al[(rm + gid + 8) * HSTR + kc];
                al[mt][2] = *(const uint32_t*)&Al[(rm + gid) * HSTR + kc + 8];
                al[mt][3] = *(const uint32_t*)&Al[(rm + gid + 8) * HSTR + kc + 8];
            }
            uint32_t bh[4][2], bl[4][2];
#pragma unroll
            for (int nt = 0; nt < 4; nt++) {
                int cn = wn * 32 + nt * 8 + gid;
                bh[nt][0] = *(const uint32_t*)&Bh[cn * HSTR + kc];
                bh[nt][1] = *(const uint32_t*)&Bh[cn * HSTR + kc + 8];
                bl[nt][0] = *(const uint32_t*)&Bl[cn * HSTR + kc];
                bl[nt][1] = *(const uint32_t*)&Bl[cn * HSTR + kc + 8];
            }
#pragma unroll
            for (int mt = 0; mt < 2; mt++)
#pragma unroll
                for (int nt = 0; nt < 4; nt++) {
                    mma_f16(acc[mt][nt], ah[mt][0], ah[mt][1], ah[mt][2], ah[mt][3],
                            bl[nt][0], bl[nt][1]);
                    mma_f16(acc[mt][nt], al[mt][0], al[mt][1], al[mt][2], al[mt][3],
                            bh[nt][0], bh[nt][1]);
                    mma_f16(acc[mt][nt], ah[mt][0], ah[mt][1], ah[mt][2], ah[mt][3],
                            bh[nt][0], bh[nt][1]);
                }
        }
    };

    int T = K / GBK;
    // prologue: stages 0..NSTAGE-2 (one commit-group each)
#pragma unroll
    for (int s = 0; s < NSTAGE - 1; s++) {
        if (s < T) loadStage(s, s);
        cp_commit();
    }
    for (int t = 0; t < T; t++) {
        int tS = t + NSTAGE - 1;
        if (tS < T) loadStage(tS, tS % NSTAGE);
        cp_commit();                 // exactly one group per iteration
        cp_wait<NSTAGE - 1>();       // stage t arrived
        __syncthreads();
        compute(t % NSTAGE);
        __syncthreads();             // all reads done before buffer refill
    }

    // epilogue: bias (+relu), guarded stores
#pragma unroll
    for (int mt = 0; mt < 2; mt++) {
        int rbase = m0 + wm * 32 + mt * 16 + gid;
#pragma unroll
        for (int nt = 0; nt < 4; nt++) {
            int c0 = n0 + wn * 32 + nt * 8 + tig * 2;
            float bia0 = bias[c0], bia1 = bias[c0 + 1];
#pragma unroll
            for (int half = 0; half < 2; half++) {
                int m = rbase + half * 8;
                if (m >= M) continue;
                float v0 = acc[mt][nt][half * 2 + 0] + bia0;
                float v1 = acc[mt][nt][half * 2 + 1] + bia1;
                if (doRelu) { v0 = fmaxf(v0, 0.f); v1 = fmaxf(v1, 0.f); }
                C[(size_t)m * N + c0] = v0;
                C[(size_t)m * N + c0 + 1] = v1;
            }
        }
    }
}

// -------- softmax(relu(h3)) warp-per-row + argmax (shuffle-only) ---------------
__global__ __launch_bounds__(256) void k_softmax(const float* __restrict__ H,
                                                 float* __restrict__ S) {
    int w = blockIdx.x * 8 + (threadIdx.x >> 5);
    int lane = threadIdx.x & 31;
    if (w >= NN) return;
    const float4* Hr = (const float4*)(H + (size_t)w * CC);
    float4 v[4];
    float vmax = -1e30f;
    int vidx = 0x7FFFFFFF;
#pragma unroll
    for (int r = 0; r < 4; r++) {
        v[r] = Hr[r * 32 + lane];
        v[r].x = fmaxf(v[r].x, 0.f);
        v[r].y = fmaxf(v[r].y, 0.f);
        v[r].z = fmaxf(v[r].z, 0.f);
        v[r].w = fmaxf(v[r].w, 0.f);
        int c0 = (r * 32 + lane) * 4;
        if (v[r].x > vmax) { vmax = v[r].x; vidx = c0 + 0; }
        if (v[r].y > vmax) { vmax = v[r].y; vidx = c0 + 1; }
        if (v[r].z > vmax) { vmax = v[r].z; vidx = c0 + 2; }
        if (v[r].w > vmax) { vmax = v[r].w; vidx = c0 + 3; }
    }
#pragma unroll
    for (int off = 16; off > 0; off >>= 1) {
        float om = __shfl_xor_sync(0xFFFFFFFFu, vmax, off);
        int oi = __shfl_xor_sync(0xFFFFFFFFu, vidx, off);
        if (om > vmax || (om == vmax && oi < vidx)) { vmax = om; vidx = oi; }
    }
    float e[16];
    float sum = 0.0f;
#pragma unroll
    for (int r = 0; r < 4; r++) {
        e[r * 4 + 0] = expf(v[r].x - vmax);
        e[r * 4 + 1] = expf(v[r].y - vmax);
        e[r * 4 + 2] = expf(v[r].z - vmax);
        e[r * 4 + 3] = expf(v[r].w - vmax);
        sum += e[r * 4 + 0] + e[r * 4 + 1] + e[r * 4 + 2] + e[r * 4 + 3];
    }
#pragma unroll
    for (int off = 16; off > 0; off >>= 1) sum += __shfl_xor_sync(0xFFFFFFFFu, sum, off);
    float inv = 1.0f / sum;
    float4* Sr = (float4*)(S + (size_t)w * CC);
#pragma unroll
    for (int r = 0; r < 4; r++)
        Sr[r * 32 + lane] = make_float4(e[r * 4 + 0] * inv, e[r * 4 + 1] * inv,
                                        e[r * 4 + 2] * inv, e[r * 4 + 3] * inv);
    if (lane == 0) g_cluster[w] = vidx;
}

// ---------------- score layer ------------------------------------------------
__global__ void k_hs(const float* __restrict__ x, const float* __restrict__ Ws) {
    int t = blockIdx.x * blockDim.x + threadIdx.x;
    int w = t >> 5, lane = t & 31;
    if (w >= NN) return;
    float a = 0.0f;
#pragma unroll
    for (int r = 0; r < 4; r++) {
        int f = lane + 32 * r;
        a += x[(size_t)w * FF + f] * Ws[f];
    }
#pragma unroll
    for (int off = 16; off > 0; off >>= 1) a += __shfl_down_sync(0xFFFFFFFFu, a, off);
    if (lane == 0) g_hs[w] = a;
}

__global__ void k_intra() {
    int t = blockIdx.x * blockDim.x + threadIdx.x;
    int i = t >> 5, lane = t & 31;
    if (i >= NN) return;
    int myc = g_cluster[i];
    int beg = g_rowstart[i], end = beg + g_cnt[i];
    int cint = 0;
    for (int j = beg + lane; j < end; j += 32)
        cint += (g_cluster[g_csr[j]] == myc) ? 1 : 0;
#pragma unroll
    for (int off = 16; off > 0; off >>= 1) cint += __shfl_down_sync(0xFFFFFFFFu, cint, off);
    if (lane == 0) {
        float iv = rsqrtf((float)cint + 1.0f);
        g_invs[i] = iv;
        g_ivh[i] = iv * g_hs[i];
        if (cint > 0) atomicOr(&g_nonempty[myc], 1);
    }
}

// score + fused per-cluster (max, first-argmax) 64-bit atomicMax
__global__ void k_score(const float* __restrict__ bs) {
    int t = blockIdx.x * blockDim.x + threadIdx.x;
    int i = t >> 5, lane = t & 31;
    if (i >= NN) return;
    int myc = g_cluster[i];
    int beg = g_rowstart[i], end = beg + g_cnt[i];
    float acc = 0.0f;
    for (int j = beg + lane; j < end; j += 32) {
        int s = g_csr[j];
        if (g_cluster[s] == myc) acc += g_ivh[s];
    }
#pragma unroll
    for (int off = 16; off > 0; off >>= 1) acc += __shfl_down_sync(0xFFFFFFFFu, acc, off);
    if (lane == 0) {
        float invi = g_invs[i];
        float score = tanhf(invi * (acc + g_ivh[i]) + bs[0]);
        unsigned long long key =
            ((unsigned long long)fkey(score) << 32) | (unsigned)(0x7FFFFFFF - i);
        atomicMax(&g_ckey[myc], key);
    }
}

// ---------------- outputs ----------------------------------------------------
__global__ void k_newx(const float* __restrict__ x, float* __restrict__ out) {
    int c = blockIdx.x, f = threadIdx.x;
    float v = 0.0f;
    if (g_nonempty[c]) {
        unsigned long long key = g_ckey[c];
        float alpha = fdec((unsigned)(key >> 32));
        int id = 0x7FFFFFFF - (int)(key & 0xFFFFFFFFull);
        v = x[(size_t)id * FF + f] * alpha;
    }
    out[(size_t)c * FF + f] = v;
}

__global__ void k_zero(float* __restrict__ p, int n) {
    int i = blockIdx.x * blockDim.x + threadIdx.x;
    if (i < n) p[i] = 0.0f;
}

__global__ void k_adj(const int* __restrict__ src, const int* __restrict__ dst,
                      float* __restrict__ adj) {
    int e = blockIdx.x * blockDim.x + threadIdx.x;
    if (e >= EE) return;
    int ci = g_cluster[src[e]], cj = g_cluster[dst[e]];
    if (ci != cj && g_nonempty[ci] && g_nonempty[cj]) adj[ci * CC + cj] = 1.0f;
}

// ---------------- host -------------------------------------------------------
extern "C" void kernel_launch(void* const* d_in, const int* in_sizes, int n_in,
                              void* d_out, int out_size) {
    const float* x  = (const float*)d_in[0];
    const int*   ei = (const int*)d_in[1];
    const int*   src = ei;
    const int*   dst = ei + EE;
    const float* W1 = (const float*)d_in[3];
    const float* b1 = (const float*)d_in[4];
    const float* W2 = (const float*)d_in[5];
    const float* b2 = (const float*)d_in[6];
    const float* W3 = (const float*)d_in[7];
    const float* b3 = (const float*)d_in[8];
    const float* Ws = (const float*)d_in[9];
    const float* bs = (const float*)d_in[10];

    float* out      = (float*)d_out;
    float* out_newx = out;
    float* out_adj  = out + (size_t)CC * FF;
    float* out_S    = out + (size_t)CC * FF + (size_t)CC * CC + CC;

    float *ph, *ph3;
    __half *pPh, *pPl, *pWth, *pWtl;
    cudaGetSymbolAddress((void**)&ph,   g_h);
    cudaGetSymbolAddress((void**)&ph3,  g_h3);
    cudaGetSymbolAddress((void**)&pPh,  g_Ph);
    cudaGetSymbolAddress((void**)&pPl,  g_Pl);
    cudaGetSymbolAddress((void**)&pWth, g_Wth);
    cudaGetSymbolAddress((void**)&pWtl, g_Wtl);

    cudaFuncSetAttribute(k_gemm_fp16, cudaFuncAttributeMaxDynamicSharedMemorySize,
                         GEMM_SMEM_BYTES);

    const int TB = 256;
    int gN = (NN + TB - 1) / TB;
    int gE = (EE + TB - 1) / TB;
    int gW = (NN * 32 + TB - 1) / TB;
    int gP = (NN + 7) / 8;
    int nbScan = (NN + 1023) / 1024;
    int gM = (NN + GBM - 1) / GBM;

    // graph build (CSR) + degree normalization
    k_init<<<gN, TB>>>();
    k_count<<<gE, TB>>>(dst);
    k_scan1<<<nbScan, 1024>>>();
    k_scan2<<<1, 32>>>(nbScan);
    k_scan3<<<gN, TB>>>();
    k_scatter<<<gE, TB>>>(src, dst);

    // 3-layer GCN: prop (writes split fp16) -> cp.async fp16x3 tensor GEMM
    dim3 tb(32, 8);
    k_prop<FF><<<gP, TB>>>(x, pPh, pPl);
    k_transW<<<dim3(HH / 32, FF / 32), tb>>>(W1, pWth, pWtl, FF, HH);
    k_gemm_fp16<<<dim3(HH / GBN, gM), 512, GEMM_SMEM_BYTES>>>(
        pPh, pPl, pWth, pWtl, b1, ph, NN, HH, FF, 1);
    k_prop<HH><<<gP, TB>>>(ph, pPh, pPl);
    k_transW<<<dim3(HH / 32, HH / 32), tb>>>(W2, pWth, pWtl, HH, HH);
    k_gemm_fp16<<<dim3(HH / GBN, gM), 512, GEMM_SMEM_BYTES>>>(
        pPh, pPl, pWth, pWtl, b2, ph, NN, HH, HH, 1);
    k_prop<HH><<<gP, TB>>>(ph, pPh, pPl);
    k_transW<<<dim3(CC / 32, HH / 32), tb>>>(W3, pWth, pWtl, HH, CC);
    k_gemm_fp16<<<dim3(CC / GBN, gM), 512, GEMM_SMEM_BYTES>>>(
        pPh, pPl, pWth, pWtl, b3, ph3, NN, CC, HH, 0);

    // softmax(relu) -> S output + hard clusters (warp-per-row)
    k_softmax<<<(NN + 7) / 8, 256>>>(ph3, out_S);

    // score layer on intra-cluster subgraph (seg-max fused into k_score)
    k_hs<<<gW, TB>>>(x, Ws);
    k_intra<<<gW, TB>>>();
    k_score<<<gW, TB>>>(bs);

    // pooled outputs
    k_newx<<<CC, FF>>>(x, out_newx);
    int zn = CC * CC + CC;
    k_zero<<<(zn + TB - 1) / TB, TB>>>(out_adj, zn);
    k_adj<<<gE, TB>>>(src, dst, out_adj);
}

// round 14
// speedup vs baseline: 1.0636x; 1.0636x over previous
#include <cuda_runtime.h>
#include <cuda_fp16.h>
#include <math.h>
#include <stdint.h>

#define NN 50000
#define FF 128
#define HH 256
#define CC 512
#define EE 800000

// ---------------- scratch (device globals; no allocation allowed) -------------
__device__ int      g_cnt[NN];
__device__ int      g_rowstart[NN];
__device__ int      g_fill[NN];
__device__ int      g_incl[NN];
__device__ int      g_bsum[64];
__device__ int      g_csr[EE];
__device__ float    g_inv[NN];
__device__ float    g_hs[NN];
__device__ float    g_invs[NN];
__device__ float    g_ivh[NN];
__device__ int      g_cluster[NN];
__device__ unsigned long long g_ckey[CC];  // (fkey(score)<<32)|(0x7FFFFFFF-i)
__device__ int      g_nonempty[CC];
__device__ float    g_P[(size_t)NN * HH];    // propagation output (<=256 feats)
__device__ float    g_h[(size_t)NN * HH];    // hidden activations
__device__ float    g_h3[(size_t)NN * CC];   // layer-3 pre-softmax
__device__ float    g_Wt1[(size_t)HH * FF];  // W1^T [N,K]
__device__ float    g_Wt2[(size_t)HH * HH];  // W2^T
__device__ float    g_Wt3[(size_t)CC * HH];  // W3^T

// monotonic float<->uint key for atomicMax on floats
__device__ __forceinline__ unsigned fkey(float f) {
    unsigned u = __float_as_uint(f);
    return (u & 0x80000000u) ? ~u : (u | 0x80000000u);
}
__device__ __forceinline__ float fdec(unsigned k) {
    return (k & 0x80000000u) ? __uint_as_float(k ^ 0x80000000u)
                             : __uint_as_float(~k);
}

// ---------------- setup kernels ----------------------------------------------
__global__ void k_init() {
    int i = blockIdx.x * blockDim.x + threadIdx.x;
    if (i < NN) g_cnt[i] = 0;
    if (i < CC) { g_ckey[i] = 0ull; g_nonempty[i] = 0; }
}

__global__ void k_count(const int* __restrict__ dst) {
    int e = blockIdx.x * blockDim.x + threadIdx.x;
    if (e < EE) atomicAdd(&g_cnt[dst[e]], 1);
}

__global__ void k_scan1() {  // per-1024 block inclusive scan of g_cnt -> g_incl
    __shared__ int s[1024];
    int g = blockIdx.x * 1024 + threadIdx.x;
    int v = (g < NN) ? g_cnt[g] : 0;
    s[threadIdx.x] = v;
    __syncthreads();
    for (int off = 1; off < 1024; off <<= 1) {
        int t = (threadIdx.x >= off) ? s[threadIdx.x - off] : 0;
        __syncthreads();
        s[threadIdx.x] += t;
        __syncthreads();
    }
    if (g < NN) g_incl[g] = s[threadIdx.x];
    if (threadIdx.x == 1023) g_bsum[blockIdx.x] = s[1023];
}

__global__ void k_scan2(int nb) {
    if (threadIdx.x == 0 && blockIdx.x == 0) {
        int a = 0;
        for (int i = 0; i < nb; i++) { int t = g_bsum[i]; g_bsum[i] = a; a += t; }
    }
}

__global__ void k_scan3() {
    int g = blockIdx.x * blockDim.x + threadIdx.x;
    if (g < NN) {
        int rs = g_incl[g] + g_bsum[g >> 10] - g_cnt[g];
        g_rowstart[g] = rs;
        g_fill[g] = rs;
        g_inv[g] = rsqrtf((float)g_cnt[g] + 1.0f);
    }
}

__global__ void k_scatter(const int* __restrict__ src, const int* __restrict__ dst) {
    int e = blockIdx.x * blockDim.x + threadIdx.x;
    if (e < EE) {
        int p = atomicAdd(&g_fill[dst[e]], 1);
        g_csr[p] = src[e];
    }
}

// ------- GCN propagation, warp-per-node, float4 --------------------------------
template <int F>
__global__ __launch_bounds__(256) void k_prop(const float* __restrict__ X,
                                              float* __restrict__ Y) {
    constexpr int V = F / 128;
    int w = blockIdx.x * (blockDim.x >> 5) + (threadIdx.x >> 5);
    int lane = threadIdx.x & 31;
    if (w >= NN) return;
    float invi = g_inv[w];
    const float4* Xw = (const float4*)(X + (size_t)w * F);
    float4 acc[V];
#pragma unroll
    for (int v = 0; v < V; v++) {
        float4 t = Xw[lane + v * 32];
        acc[v] = make_float4(invi * t.x, invi * t.y, invi * t.z, invi * t.w);
    }
    int beg = g_rowstart[w];
    int end = beg + g_cnt[w];
    int j = beg;
    for (; j + 4 <= end; j += 4) {
        int s0 = g_csr[j], s1 = g_csr[j + 1], s2 = g_csr[j + 2], s3 = g_csr[j + 3];
        float w0 = g_inv[s0], w1 = g_inv[s1], w2 = g_inv[s2], w3 = g_inv[s3];
        const float4* r0 = (const float4*)(X + (size_t)s0 * F);
        const float4* r1 = (const float4*)(X + (size_t)s1 * F);
        const float4* r2 = (const float4*)(X + (size_t)s2 * F);
        const float4* r3 = (const float4*)(X + (size_t)s3 * F);
#pragma unroll
        for (int v = 0; v < V; v++) {
            float4 t0 = r0[lane + v * 32];
            float4 t1 = r1[lane + v * 32];
            float4 t2 = r2[lane + v * 32];
            float4 t3 = r3[lane + v * 32];
            acc[v].x += w0 * t0.x + w1 * t1.x + w2 * t2.x + w3 * t3.x;
            acc[v].y += w0 * t0.y + w1 * t1.y + w2 * t2.y + w3 * t3.y;
            acc[v].z += w0 * t0.z + w1 * t1.z + w2 * t2.z + w3 * t3.z;
            acc[v].w += w0 * t0.w + w1 * t1.w + w2 * t2.w + w3 * t3.w;
        }
    }
    for (; j < end; j++) {
        int s0 = g_csr[j];
        float w0 = g_inv[s0];
        const float4* r0 = (const float4*)(X + (size_t)s0 * F);
#pragma unroll
        for (int v = 0; v < V; v++) {
            float4 t0 = r0[lane + v * 32];
            acc[v].x += w0 * t0.x; acc[v].y += w0 * t0.y;
            acc[v].z += w0 * t0.z; acc[v].w += w0 * t0.w;
        }
    }
    float4* Yw = (float4*)(Y + (size_t)w * F);
#pragma unroll
    for (int v = 0; v < V; v++) {
        Yw[lane + v * 32] = make_float4(invi * acc[v].x, invi * acc[v].y,
                                        invi * acc[v].z, invi * acc[v].w);
    }
}

// ---------------- weight transpose W[K,N] -> Wt[N,K] ---------------------------
__global__ void k_transW(const float* __restrict__ W, float* __restrict__ Wt,
                         int K, int N) {
    __shared__ float tile[32][33];
    int n0 = blockIdx.x * 32, k0 = blockIdx.y * 32;
    int tx = threadIdx.x, ty = threadIdx.y;  // 32 x 8
#pragma unroll
    for (int i = 0; i < 4; i++)
        tile[ty + i * 8][tx] = W[(size_t)(k0 + ty + i * 8) * N + n0 + tx];
    __syncthreads();
#pragma unroll
    for (int i = 0; i < 4; i++)
        Wt[(size_t)(n0 + ty + i * 8) * K + k0 + tx] = tile[tx][ty + i * 8];
}

// ---------------- fp16x3 tensor-core GEMM (round-11 known-good) ----------------
// C[M,N] = A[M,K] @ Bt[N,K]^T + bias, optional relu.
#define GBM 128
#define GBN 128
#define GBK 32
#define HSTR 40                     // halves per smem row (32 + 8 pad)
#define HTILE (128 * HSTR)
#define BUFH (4 * HTILE)            // Ah, Al, Bh, Bl
#define GEMM_SMEM_BYTES (2 * BUFH * 2)   // 81920

__device__ __forceinline__ void f16_split(float v, __half& hi, __half& lo) {
    hi = __float2half_rn(v);
    lo = __float2half_rn(v - __half2float(hi));
}

__device__ __forceinline__ void mma_f16(float c[4], uint32_t a0, uint32_t a1,
                                        uint32_t a2, uint32_t a3,
                                        uint32_t b0, uint32_t b1) {
    asm volatile(
        "mma.sync.aligned.m16n8k16.row.col.f32.f16.f16.f32 "
        "{%0,%1,%2,%3}, {%4,%5,%6,%7}, {%8,%9}, {%0,%1,%2,%3};"
        : "+f"(c[0]), "+f"(c[1]), "+f"(c[2]), "+f"(c[3])
        : "r"(a0), "r"(a1), "r"(a2), "r"(a3), "r"(b0), "r"(b1));
}

__global__ __launch_bounds__(512, 1) void k_gemm_fp16(
    const float* __restrict__ A, const float* __restrict__ Bt,
    const float* __restrict__ bias, float* __restrict__ C,
    int M, int N, int K, int doRelu) {
    extern __shared__ __half hsm[];

    int tid = threadIdx.x;
    int warp = tid >> 5;
    int lane = tid & 31;
    int gid = lane >> 2;
    int tig = lane & 3;
    int wm = warp >> 2;
    int wn = warp & 3;

    int m0 = blockIdx.y * GBM;
    int n0 = blockIdx.x * GBN;

    float acc[2][4][4];
#pragma unroll
    for (int mt = 0; mt < 2; mt++)
#pragma unroll
        for (int nt = 0; nt < 4; nt++)
#pragma unroll
            for (int r = 0; r < 4; r++) acc[mt][nt][r] = 0.0f;

    int g_r = tid >> 3;
    int g_c = (tid & 7) * 4;

    float4 arv[2], brv[2];

    auto loadG = [&](int t) {
        int k0 = t * GBK;
#pragma unroll
        for (int p = 0; p < 2; p++) {
            int m = m0 + g_r + p * 64;
            arv[p] = make_float4(0.f, 0.f, 0.f, 0.f);
            if (m < M) arv[p] = *(const float4*)&A[(size_t)m * K + k0 + g_c];
            brv[p] = *(const float4*)&Bt[(size_t)(n0 + g_r + p * 64) * K + k0 + g_c];
        }
    };

    auto storeSplit = [&](int buf) {
        __half* Ah = hsm + buf * BUFH;
        __half* Al = Ah + HTILE;
        __half* Bh = Al + HTILE;
        __half* Bl = Bh + HTILE;
#pragma unroll
        for (int p = 0; p < 2; p++) {
            int row = g_r + p * 64;
            __half h0, l0, h1, l1, h2, l2, h3, l3;
            f16_split(arv[p].x, h0, l0); f16_split(arv[p].y, h1, l1);
            f16_split(arv[p].z, h2, l2); f16_split(arv[p].w, h3, l3);
            __half2* pa = (__half2*)&Ah[row * HSTR + g_c];
            pa[0] = __halves2half2(h0, h1); pa[1] = __halves2half2(h2, h3);
            __half2* pal = (__half2*)&Al[row * HSTR + g_c];
            pal[0] = __halves2half2(l0, l1); pal[1] = __halves2half2(l2, l3);
            f16_split(brv[p].x, h0, l0); f16_split(brv[p].y, h1, l1);
            f16_split(brv[p].z, h2, l2); f16_split(brv[p].w, h3, l3);
            __half2* pb = (__half2*)&Bh[row * HSTR + g_c];
            pb[0] = __halves2half2(h0, h1); pb[1] = __halves2half2(h2, h3);
            __half2* pbl = (__half2*)&Bl[row * HSTR + g_c];
            pbl[0] = __halves2half2(l0, l1); pbl[1] = __halves2half2(l2, l3);
        }
    };

    auto compute = [&](int buf) {
        const __half* Ah = hsm + buf * BUFH;
        const __half* Al = Ah + HTILE;
        const __half* Bh = Al + HTILE;
        const __half* Bl = Bh + HTILE;
#pragma unroll
        for (int ks = 0; ks < GBK / 16; ks++) {
            int kc = ks * 16 + 2 * tig;
            uint32_t ah[2][4], al[2][4];
#pragma unroll
            for (int mt = 0; mt < 2; mt++) {
                int rm = wm * 32 + mt * 16;
                ah[mt][0] = *(const uint32_t*)&Ah[(rm + gid) * HSTR + kc];
                ah[mt][1] = *(const uint32_t*)&Ah[(rm + gid + 8) * HSTR + kc];
                ah[mt][2] = *(const uint32_t*)&Ah[(rm + gid) * HSTR + kc + 8];
                ah[mt][3] = *(const uint32_t*)&Ah[(rm + gid + 8) * HSTR + kc + 8];
                al[mt][0] = *(const uint32_t*)&Al[(rm + gid) * HSTR + kc];
                al[mt][1] = *(const uint32_t*)&Al[(rm + gid + 8) * HSTR + kc];
                al[mt][2] = *(const uint32_t*)&Al[(rm + gid) * HSTR + kc + 8];
                al[mt][3] = *(const uint32_t*)&Al[(rm + gid + 8) * HSTR + kc + 8];
            }
            uint32_t bh[4][2], bl[4][2];
#pragma unroll
            for (int nt = 0; nt < 4; nt++) {
                int cn = wn * 32 + nt * 8 + gid;
                bh[nt][0] = *(const uint32_t*)&Bh[cn * HSTR + kc];
                bh[nt][1] = *(const uint32_t*)&Bh[cn * HSTR + kc + 8];
                bl[nt][0] = *(const uint32_t*)&Bl[cn * HSTR + kc];
                bl[nt][1] = *(const uint32_t*)&Bl[cn * HSTR + kc + 8];
            }
#pragma unroll
            for (int mt = 0; mt < 2; mt++)
#pragma unroll
                for (int nt = 0; nt < 4; nt++) {
                    mma_f16(acc[mt][nt], ah[mt][0], ah[mt][1], ah[mt][2], ah[mt][3],
                            bl[nt][0], bl[nt][1]);
                    mma_f16(acc[mt][nt], al[mt][0], al[mt][1], al[mt][2], al[mt][3],
                            bh[nt][0], bh[nt][1]);
                    mma_f16(acc[mt][nt], ah[mt][0], ah[mt][1], ah[mt][2], ah[mt][3],
                            bh[nt][0], bh[nt][1]);
                }
        }
    };

    int T = K / GBK;
    loadG(0);
    storeSplit(0);
    __syncthreads();
    for (int t = 0; t < T; t++) {
        int buf = t & 1;
        bool more = (t + 1 < T);
        if (more) loadG(t + 1);
        compute(buf);
        if (more) storeSplit(buf ^ 1);
        __syncthreads();
    }

#pragma unroll
    for (int mt = 0; mt < 2; mt++) {
        int rbase = m0 + wm * 32 + mt * 16 + gid;
#pragma unroll
        for (int nt = 0; nt < 4; nt++) {
            int c0 = n0 + wn * 32 + nt * 8 + tig * 2;
            float bia0 = bias[c0], bia1 = bias[c0 + 1];
#pragma unroll
            for (int half = 0; half < 2; half++) {
                int m = rbase + half * 8;
                if (m >= M) continue;
                float v0 = acc[mt][nt][half * 2 + 0] + bia0;
                float v1 = acc[mt][nt][half * 2 + 1] + bia1;
                if (doRelu) { v0 = fmaxf(v0, 0.f); v1 = fmaxf(v1, 0.f); }
                C[(size_t)m * N + c0] = v0;
                C[(size_t)m * N + c0 + 1] = v1;
            }
        }
    }
}

// -------- softmax(relu(h3)) warp-per-row + argmax (shuffle-only) ---------------
__global__ __launch_bounds__(256) void k_softmax(const float* __restrict__ H,
                                                 float* __restrict__ S) {
    int w = blockIdx.x * 8 + (threadIdx.x >> 5);
    int lane = threadIdx.x & 31;
    if (w >= NN) return;
    const float4* Hr = (const float4*)(H + (size_t)w * CC);
    float4 v[4];
    float vmax = -1e30f;
    int vidx = 0x7FFFFFFF;
#pragma unroll
    for (int r = 0; r < 4; r++) {
        v[r] = Hr[r * 32 + lane];
        v[r].x = fmaxf(v[r].x, 0.f);
        v[r].y = fmaxf(v[r].y, 0.f);
        v[r].z = fmaxf(v[r].z, 0.f);
        v[r].w = fmaxf(v[r].w, 0.f);
        int c0 = (r * 32 + lane) * 4;
        if (v[r].x > vmax) { vmax = v[r].x; vidx = c0 + 0; }
        if (v[r].y > vmax) { vmax = v[r].y; vidx = c0 + 1; }
        if (v[r].z > vmax) { vmax = v[r].z; vidx = c0 + 2; }
        if (v[r].w > vmax) { vmax = v[r].w; vidx = c0 + 3; }
    }
#pragma unroll
    for (int off = 16; off > 0; off >>= 1) {
        float om = __shfl_xor_sync(0xFFFFFFFFu, vmax, off);
        int oi = __shfl_xor_sync(0xFFFFFFFFu, vidx, off);
        if (om > vmax || (om == vmax && oi < vidx)) { vmax = om; vidx = oi; }
    }
    float e[16];
    float sum = 0.0f;
#pragma unroll
    for (int r = 0; r < 4; r++) {
        e[r * 4 + 0] = expf(v[r].x - vmax);
        e[r * 4 + 1] = expf(v[r].y - vmax);
        e[r * 4 + 2] = expf(v[r].z - vmax);
        e[r * 4 + 3] = expf(v[r].w - vmax);
        sum += e[r * 4 + 0] + e[r * 4 + 1] + e[r * 4 + 2] + e[r * 4 + 3];
    }
#pragma unroll
    for (int off = 16; off > 0; off >>= 1) sum += __shfl_xor_sync(0xFFFFFFFFu, sum, off);
    float inv = 1.0f / sum;
    float4* Sr = (float4*)(S + (size_t)w * CC);
#pragma unroll
    for (int r = 0; r < 4; r++)
        Sr[r * 32 + lane] = make_float4(e[r * 4 + 0] * inv, e[r * 4 + 1] * inv,
                                        e[r * 4 + 2] * inv, e[r * 4 + 3] * inv);
    if (lane == 0) g_cluster[w] = vidx;
}

// ---------------- score layer ------------------------------------------------
__global__ void k_hs(const float* __restrict__ x, const float* __restrict__ Ws) {
    int t = blockIdx.x * blockDim.x + threadIdx.x;
    int w = t >> 5, lane = t & 31;
    if (w >= NN) return;
    float a = 0.0f;
#pragma unroll
    for (int r = 0; r < 4; r++) {
        int f = lane + 32 * r;
        a += x[(size_t)w * FF + f] * Ws[f];
    }
#pragma unroll
    for (int off = 16; off > 0; off >>= 1) a += __shfl_down_sync(0xFFFFFFFFu, a, off);
    if (lane == 0) g_hs[w] = a;
}

__global__ void k_intra() {
    int t = blockIdx.x * blockDim.x + threadIdx.x;
    int i = t >> 5, lane = t & 31;
    if (i >= NN) return;
    int myc = g_cluster[i];
    int beg = g_rowstart[i], end = beg + g_cnt[i];
    int cint = 0;
    for (int j = beg + lane; j < end; j += 32)
        cint += (g_cluster[g_csr[j]] == myc) ? 1 : 0;
#pragma unroll
    for (int off = 16; off > 0; off >>= 1) cint += __shfl_down_sync(0xFFFFFFFFu, cint, off);
    if (lane == 0) {
        float iv = rsqrtf((float)cint + 1.0f);
        g_invs[i] = iv;
        g_ivh[i] = iv * g_hs[i];
        if (cint > 0) atomicOr(&g_nonempty[myc], 1);
    }
}

// score + fused per-cluster (max, first-argmax) 64-bit atomicMax
__global__ void k_score(const float* __restrict__ bs) {
    int t = blockIdx.x * blockDim.x + threadIdx.x;
    int i = t >> 5, lane = t & 31;
    if (i >= NN) return;
    int myc = g_cluster[i];
    int beg = g_rowstart[i], end = beg + g_cnt[i];
    float acc = 0.0f;
    for (int j = beg + lane; j < end; j += 32) {
        int s = g_csr[j];
        if (g_cluster[s] == myc) acc += g_ivh[s];
    }
#pragma unroll
    for (int off = 16; off > 0; off >>= 1) acc += __shfl_down_sync(0xFFFFFFFFu, acc, off);
    if (lane == 0) {
        float invi = g_invs[i];
        float score = tanhf(invi * (acc + g_ivh[i]) + bs[0]);
        unsigned long long key =
            ((unsigned long long)fkey(score) << 32) | (unsigned)(0x7FFFFFFF - i);
        atomicMax(&g_ckey[myc], key);
    }
}

// ---------------- outputs ----------------------------------------------------
__global__ void k_newx(const float* __restrict__ x, float* __restrict__ out) {
    int c = blockIdx.x, f = threadIdx.x;
    float v = 0.0f;
    if (g_nonempty[c]) {
        unsigned long long key = g_ckey[c];
        float alpha = fdec((unsigned)(key >> 32));
        int id = 0x7FFFFFFF - (int)(key & 0xFFFFFFFFull);
        v = x[(size_t)id * FF + f] * alpha;
    }
    out[(size_t)c * FF + f] = v;
}

__global__ void k_zero(float* __restrict__ p, int n) {
    int i = blockIdx.x * blockDim.x + threadIdx.x;
    if (i < n) p[i] = 0.0f;
}

__global__ void k_adj(const int* __restrict__ src, const int* __restrict__ dst,
                      float* __restrict__ adj) {
    int e = blockIdx.x * blockDim.x + threadIdx.x;
    if (e >= EE) return;
    int ci = g_cluster[src[e]], cj = g_cluster[dst[e]];
    if (ci != cj && g_nonempty[ci] && g_nonempty[cj]) adj[ci * CC + cj] = 1.0f;
}

// ---------------- host -------------------------------------------------------
extern "C" void kernel_launch(void* const* d_in, const int* in_sizes, int n_in,
                              void* d_out, int out_size) {
    const float* x  = (const float*)d_in[0];
    const int*   ei = (const int*)d_in[1];
    const int*   src = ei;
    const int*   dst = ei + EE;
    const float* W1 = (const float*)d_in[3];
    const float* b1 = (const float*)d_in[4];
    const float* W2 = (const float*)d_in[5];
    const float* b2 = (const float*)d_in[6];
    const float* W3 = (const float*)d_in[7];
    const float* b3 = (const float*)d_in[8];
    const float* Ws = (const float*)d_in[9];
    const float* bs = (const float*)d_in[10];

    float* out      = (float*)d_out;
    float* out_newx = out;
    float* out_adj  = out + (size_t)CC * FF;
    float* out_S    = out + (size_t)CC * FF + (size_t)CC * CC + CC;

    float *pP, *ph, *ph3, *pWt1, *pWt2, *pWt3;
    cudaGetSymbolAddress((void**)&pP,   g_P);
    cudaGetSymbolAddress((void**)&ph,   g_h);
    cudaGetSymbolAddress((void**)&ph3,  g_h3);
    cudaGetSymbolAddress((void**)&pWt1, g_Wt1);
    cudaGetSymbolAddress((void**)&pWt2, g_Wt2);
    cudaGetSymbolAddress((void**)&pWt3, g_Wt3);

    cudaFuncSetAttribute(k_gemm_fp16, cudaFuncAttributeMaxDynamicSharedMemorySize,
                         GEMM_SMEM_BYTES);

    const int TB = 256;
    int gN = (NN + TB - 1) / TB;
    int gE = (EE + TB - 1) / TB;
    int gW = (NN * 32 + TB - 1) / TB;
    int gP = (NN + 7) / 8;
    int nbScan = (NN + 1023) / 1024;
    int gM = (NN + GBM - 1) / GBM;

    // --- fork a side stream: weight transposes + k_hs run concurrently with
    // --- the CSR build (all independent of it). Captured via event fork/join.
    cudaStream_t s2;
    cudaStreamCreate(&s2);
    cudaEvent_t eFork, eJoin;
    cudaEventCreateWithFlags(&eFork, cudaEventDisableTiming);
    cudaEventCreateWithFlags(&eJoin, cudaEventDisableTiming);
    cudaEventRecord(eFork, 0);
    cudaStreamWaitEvent(s2, eFork, 0);

    dim3 tb(32, 8);
    k_transW<<<dim3(HH / 32, FF / 32), tb, 0, s2>>>(W1, pWt1, FF, HH);
    k_transW<<<dim3(HH / 32, HH / 32), tb, 0, s2>>>(W2, pWt2, HH, HH);
    k_transW<<<dim3(CC / 32, HH / 32), tb, 0, s2>>>(W3, pWt3, HH, CC);
    k_hs<<<gW, TB, 0, s2>>>(x, Ws);
    cudaEventRecord(eJoin, s2);

    // graph build (CSR) + degree normalization (main stream)
    k_init<<<gN, TB>>>();
    k_count<<<gE, TB>>>(dst);
    k_scan1<<<nbScan, 1024>>>();
    k_scan2<<<1, 32>>>(nbScan);
    k_scan3<<<gN, TB>>>();
    k_scatter<<<gE, TB>>>(src, dst);

    // 3-layer GCN: propagate (input space) -> fp16x3 tensor-core linear
    k_prop<FF><<<gP, TB>>>(x, pP);
    cudaStreamWaitEvent(0, eJoin, 0);   // join: weights + hs ready
    k_gemm_fp16<<<dim3(HH / GBN, gM), 512, GEMM_SMEM_BYTES>>>(pP, pWt1, b1, ph, NN, HH, FF, 1);
    k_prop<HH><<<gP, TB>>>(ph, pP);
    k_gemm_fp16<<<dim3(HH / GBN, gM), 512, GEMM_SMEM_BYTES>>>(pP, pWt2, b2, ph, NN, HH, HH, 1);
    k_prop<HH><<<gP, TB>>>(ph, pP);
    k_gemm_fp16<<<dim3(CC / GBN, gM), 512, GEMM_SMEM_BYTES>>>(pP, pWt3, b3, ph3, NN, CC, HH, 0);

    // softmax(relu) -> S output + hard clusters (warp-per-row)
    k_softmax<<<(NN + 7) / 8, 256>>>(ph3, out_S);

    // score layer on intra-cluster subgraph (seg-max fused into k_score)
    k_intra<<<gW, TB>>>();
    k_score<<<gW, TB>>>(bs);

    // pooled outputs
    k_newx<<<CC, FF>>>(x, out_newx);
    int zn = CC * CC + CC;
    k_zero<<<(zn + TB - 1) / TB, TB>>>(out_adj, zn);
    k_adj<<<gE, TB>>>(src, dst, out_adj);
}

// round 15
// speedup vs baseline: 1.0735x; 1.0093x over previous
#include <cuda_runtime.h>
#include <cuda_fp16.h>
#include <math.h>
#include <stdint.h>

#define NN 50000
#define FF 128
#define HH 256
#define CC 512
#define EE 800000

// ---------------- scratch (device globals; no allocation allowed) -------------
__device__ int      g_cnt[NN];
__device__ int      g_rowstart[NN];
__device__ int      g_fill[NN];
__device__ int      g_incl[NN];
__device__ int      g_bsum[64];
__device__ int      g_csr[EE];
__device__ float    g_inv[NN];
__device__ float    g_hs[NN];
__device__ float    g_invs[NN];
__device__ float    g_ivh[NN];
__device__ int      g_cluster[NN];
__device__ unsigned long long g_ckey[CC];  // (fkey(score)<<32)|(0x7FFFFFFF-i)
__device__ int      g_nonempty[CC];
__device__ float    g_P[(size_t)NN * HH];    // propagation output (<=256 feats)
__device__ float    g_h[(size_t)NN * HH];    // hidden activations
__device__ float    g_h3[(size_t)NN * CC];   // layer-3 pre-softmax
__device__ float    g_Wt1[(size_t)HH * FF];  // W1^T [N,K]
__device__ float    g_Wt2[(size_t)HH * HH];  // W2^T
__device__ float    g_Wt3[(size_t)CC * HH];  // W3^T

// monotonic float<->uint key for atomicMax on floats
__device__ __forceinline__ unsigned fkey(float f) {
    unsigned u = __float_as_uint(f);
    return (u & 0x80000000u) ? ~u : (u | 0x80000000u);
}
__device__ __forceinline__ float fdec(unsigned k) {
    return (k & 0x80000000u) ? __uint_as_float(k ^ 0x80000000u)
                             : __uint_as_float(~k);
}

// ---------------- setup kernels ----------------------------------------------
__global__ void k_init() {
    int i = blockIdx.x * blockDim.x + threadIdx.x;
    if (i < NN) g_cnt[i] = 0;
    if (i < CC) { g_ckey[i] = 0ull; g_nonempty[i] = 0; }
}

__global__ void k_count(const int* __restrict__ dst) {
    int e = blockIdx.x * blockDim.x + threadIdx.x;
    if (e < EE) atomicAdd(&g_cnt[dst[e]], 1);
}

__global__ void k_scan1() {  // per-1024 block inclusive scan of g_cnt -> g_incl
    __shared__ int s[1024];
    int g = blockIdx.x * 1024 + threadIdx.x;
    int v = (g < NN) ? g_cnt[g] : 0;
    s[threadIdx.x] = v;
    __syncthreads();
    for (int off = 1; off < 1024; off <<= 1) {
        int t = (threadIdx.x >= off) ? s[threadIdx.x - off] : 0;
        __syncthreads();
        s[threadIdx.x] += t;
        __syncthreads();
    }
    if (g < NN) g_incl[g] = s[threadIdx.x];
    if (threadIdx.x == 1023) g_bsum[blockIdx.x] = s[1023];
}

// scan of block sums folded in: each thread sums g_bsum[0..blk-1] from smem
__global__ void k_scan3(int nb) {
    __shared__ int bs[64];
    int t = threadIdx.x;
    if (t < 64) bs[t] = (t < nb) ? g_bsum[t] : 0;
    __syncthreads();
    int g = blockIdx.x * blockDim.x + t;
    if (g < NN) {
        int blk = g >> 10;
        int pre = 0;
        for (int j = 0; j < blk; j++) pre += bs[j];
        int rs = g_incl[g] + pre - g_cnt[g];
        g_rowstart[g] = rs;
        g_fill[g] = rs;
        g_inv[g] = rsqrtf((float)g_cnt[g] + 1.0f);
    }
}

__global__ void k_scatter(const int* __restrict__ src, const int* __restrict__ dst) {
    int e = blockIdx.x * blockDim.x + threadIdx.x;
    if (e < EE) {
        int p = atomicAdd(&g_fill[dst[e]], 1);
        g_csr[p] = src[e];
    }
}

// ------- GCN propagation, warp-per-node, float4 --------------------------------
template <int F>
__global__ __launch_bounds__(256) void k_prop(const float* __restrict__ X,
                                              float* __restrict__ Y) {
    constexpr int V = F / 128;
    int w = blockIdx.x * (blockDim.x >> 5) + (threadIdx.x >> 5);
    int lane = threadIdx.x & 31;
    if (w >= NN) return;
    float invi = g_inv[w];
    const float4* Xw = (const float4*)(X + (size_t)w * F);
    float4 acc[V];
#pragma unroll
    for (int v = 0; v < V; v++) {
        float4 t = Xw[lane + v * 32];
        acc[v] = make_float4(invi * t.x, invi * t.y, invi * t.z, invi * t.w);
    }
    int beg = g_rowstart[w];
    int end = beg + g_cnt[w];
    int j = beg;
    for (; j + 4 <= end; j += 4) {
        int s0 = g_csr[j], s1 = g_csr[j + 1], s2 = g_csr[j + 2], s3 = g_csr[j + 3];
        float w0 = g_inv[s0], w1 = g_inv[s1], w2 = g_inv[s2], w3 = g_inv[s3];
        const float4* r0 = (const float4*)(X + (size_t)s0 * F);
        const float4* r1 = (const float4*)(X + (size_t)s1 * F);
        const float4* r2 = (const float4*)(X + (size_t)s2 * F);
        const float4* r3 = (const float4*)(X + (size_t)s3 * F);
#pragma unroll
        for (int v = 0; v < V; v++) {
            float4 t0 = r0[lane + v * 32];
            float4 t1 = r1[lane + v * 32];
            float4 t2 = r2[lane + v * 32];
            float4 t3 = r3[lane + v * 32];
            acc[v].x += w0 * t0.x + w1 * t1.x + w2 * t2.x + w3 * t3.x;
            acc[v].y += w0 * t0.y + w1 * t1.y + w2 * t2.y + w3 * t3.y;
            acc[v].z += w0 * t0.z + w1 * t1.z + w2 * t2.z + w3 * t3.z;
            acc[v].w += w0 * t0.w + w1 * t1.w + w2 * t2.w + w3 * t3.w;
        }
    }
    for (; j < end; j++) {
        int s0 = g_csr[j];
        float w0 = g_inv[s0];
        const float4* r0 = (const float4*)(X + (size_t)s0 * F);
#pragma unroll
        for (int v = 0; v < V; v++) {
            float4 t0 = r0[lane + v * 32];
            acc[v].x += w0 * t0.x; acc[v].y += w0 * t0.y;
            acc[v].z += w0 * t0.z; acc[v].w += w0 * t0.w;
        }
    }
    float4* Yw = (float4*)(Y + (size_t)w * F);
#pragma unroll
    for (int v = 0; v < V; v++) {
        Yw[lane + v * 32] = make_float4(invi * acc[v].x, invi * acc[v].y,
                                        invi * acc[v].z, invi * acc[v].w);
    }
}

// ---------------- weight transpose W[K,N] -> Wt[N,K] ---------------------------
__global__ void k_transW(const float* __restrict__ W, float* __restrict__ Wt,
                         int K, int N) {
    __shared__ float tile[32][33];
    int n0 = blockIdx.x * 32, k0 = blockIdx.y * 32;
    int tx = threadIdx.x, ty = threadIdx.y;  // 32 x 8
#pragma unroll
    for (int i = 0; i < 4; i++)
        tile[ty + i * 8][tx] = W[(size_t)(k0 + ty + i * 8) * N + n0 + tx];
    __syncthreads();
#pragma unroll
    for (int i = 0; i < 4; i++)
        Wt[(size_t)(n0 + ty + i * 8) * K + k0 + tx] = tile[tx][ty + i * 8];
}

// ---------------- fp16x3 tensor-core GEMM (known-good) -------------------------
// C[M,N] = A[M,K] @ Bt[N,K]^T + bias, optional relu.
#define GBM 128
#define GBN 128
#define GBK 32
#define HSTR 40                     // halves per smem row (32 + 8 pad)
#define HTILE (128 * HSTR)
#define BUFH (4 * HTILE)            // Ah, Al, Bh, Bl
#define GEMM_SMEM_BYTES (2 * BUFH * 2)   // 81920

__device__ __forceinline__ void f16_split(float v, __half& hi, __half& lo) {
    hi = __float2half_rn(v);
    lo = __float2half_rn(v - __half2float(hi));
}

__device__ __forceinline__ void mma_f16(float c[4], uint32_t a0, uint32_t a1,
                                        uint32_t a2, uint32_t a3,
                                        uint32_t b0, uint32_t b1) {
    asm volatile(
        "mma.sync.aligned.m16n8k16.row.col.f32.f16.f16.f32 "
        "{%0,%1,%2,%3}, {%4,%5,%6,%7}, {%8,%9}, {%0,%1,%2,%3};"
        : "+f"(c[0]), "+f"(c[1]), "+f"(c[2]), "+f"(c[3])
        : "r"(a0), "r"(a1), "r"(a2), "r"(a3), "r"(b0), "r"(b1));
}

__global__ __launch_bounds__(512, 1) void k_gemm_fp16(
    const float* __restrict__ A, const float* __restrict__ Bt,
    const float* __restrict__ bias, float* __restrict__ C,
    int M, int N, int K, int doRelu) {
    extern __shared__ __half hsm[];

    int tid = threadIdx.x;
    int warp = tid >> 5;
    int lane = tid & 31;
    int gid = lane >> 2;
    int tig = lane & 3;
    int wm = warp >> 2;
    int wn = warp & 3;

    int m0 = blockIdx.y * GBM;
    int n0 = blockIdx.x * GBN;

    float acc[2][4][4];
#pragma unroll
    for (int mt = 0; mt < 2; mt++)
#pragma unroll
        for (int nt = 0; nt < 4; nt++)
#pragma unroll
            for (int r = 0; r < 4; r++) acc[mt][nt][r] = 0.0f;

    int g_r = tid >> 3;
    int g_c = (tid & 7) * 4;

    float4 arv[2], brv[2];

    auto loadG = [&](int t) {
        int k0 = t * GBK;
#pragma unroll
        for (int p = 0; p < 2; p++) {
            int m = m0 + g_r + p * 64;
            arv[p] = make_float4(0.f, 0.f, 0.f, 0.f);
            if (m < M) arv[p] = *(const float4*)&A[(size_t)m * K + k0 + g_c];
            brv[p] = *(const float4*)&Bt[(size_t)(n0 + g_r + p * 64) * K + k0 + g_c];
        }
    };

    auto storeSplit = [&](int buf) {
        __half* Ah = hsm + buf * BUFH;
        __half* Al = Ah + HTILE;
        __half* Bh = Al + HTILE;
        __half* Bl = Bh + HTILE;
#pragma unroll
        for (int p = 0; p < 2; p++) {
            int row = g_r + p * 64;
            __half h0, l0, h1, l1, h2, l2, h3, l3;
            f16_split(arv[p].x, h0, l0); f16_split(arv[p].y, h1, l1);
            f16_split(arv[p].z, h2, l2); f16_split(arv[p].w, h3, l3);
            __half2* pa = (__half2*)&Ah[row * HSTR + g_c];
            pa[0] = __halves2half2(h0, h1); pa[1] = __halves2half2(h2, h3);
            __half2* pal = (__half2*)&Al[row * HSTR + g_c];
            pal[0] = __halves2half2(l0, l1); pal[1] = __halves2half2(l2, l3);
            f16_split(brv[p].x, h0, l0); f16_split(brv[p].y, h1, l1);
            f16_split(brv[p].z, h2, l2); f16_split(brv[p].w, h3, l3);
            __half2* pb = (__half2*)&Bh[row * HSTR + g_c];
            pb[0] = __halves2half2(h0, h1); pb[1] = __halves2half2(h2, h3);
            __half2* pbl = (__half2*)&Bl[row * HSTR + g_c];
            pbl[0] = __halves2half2(l0, l1); pbl[1] = __halves2half2(l2, l3);
        }
    };

    auto compute = [&](int buf) {
        const __half* Ah = hsm + buf * BUFH;
        const __half* Al = Ah + HTILE;
        const __half* Bh = Al + HTILE;
        const __half* Bl = Bh + HTILE;
#pragma unroll
        for (int ks = 0; ks < GBK / 16; ks++) {
            int kc = ks * 16 + 2 * tig;
            uint32_t ah[2][4], al[2][4];
#pragma unroll
            for (int mt = 0; mt < 2; mt++) {
                int rm = wm * 32 + mt * 16;
                ah[mt][0] = *(const uint32_t*)&Ah[(rm + gid) * HSTR + kc];
                ah[mt][1] = *(const uint32_t*)&Ah[(rm + gid + 8) * HSTR + kc];
                ah[mt][2] = *(const uint32_t*)&Ah[(rm + gid) * HSTR + kc + 8];
                ah[mt][3] = *(const uint32_t*)&Ah[(rm + gid + 8) * HSTR + kc + 8];
                al[mt][0] = *(const uint32_t*)&Al[(rm + gid) * HSTR + kc];
                al[mt][1] = *(const uint32_t*)&Al[(rm + gid + 8) * HSTR + kc];
                al[mt][2] = *(const uint32_t*)&Al[(rm + gid) * HSTR + kc + 8];
                al[mt][3] = *(const uint32_t*)&Al[(rm + gid + 8) * HSTR + kc + 8];
            }
            uint32_t bh[4][2], bl[4][2];
#pragma unroll
            for (int nt = 0; nt < 4; nt++) {
                int cn = wn * 32 + nt * 8 + gid;
                bh[nt][0] = *(const uint32_t*)&Bh[cn * HSTR + kc];
                bh[nt][1] = *(const uint32_t*)&Bh[cn * HSTR + kc + 8];
                bl[nt][0] = *(const uint32_t*)&Bl[cn * HSTR + kc];
                bl[nt][1] = *(const uint32_t*)&Bl[cn * HSTR + kc + 8];
            }
#pragma unroll
            for (int mt = 0; mt < 2; mt++)
#pragma unroll
                for (int nt = 0; nt < 4; nt++) {
                    mma_f16(acc[mt][nt], ah[mt][0], ah[mt][1], ah[mt][2], ah[mt][3],
                            bl[nt][0], bl[nt][1]);
                    mma_f16(acc[mt][nt], al[mt][0], al[mt][1], al[mt][2], al[mt][3],
                            bh[nt][0], bh[nt][1]);
                    mma_f16(acc[mt][nt], ah[mt][0], ah[mt][1], ah[mt][2], ah[mt][3],
                            bh[nt][0], bh[nt][1]);
                }
        }
    };

    int T = K / GBK;
    loadG(0);
    storeSplit(0);
    __syncthreads();
    for (int t = 0; t < T; t++) {
        int buf = t & 1;
        bool more = (t + 1 < T);
        if (more) loadG(t + 1);
        compute(buf);
        if (more) storeSplit(buf ^ 1);
        __syncthreads();
    }

#pragma unroll
    for (int mt = 0; mt < 2; mt++) {
        int rbase = m0 + wm * 32 + mt * 16 + gid;
#pragma unroll
        for (int nt = 0; nt < 4; nt++) {
            int c0 = n0 + wn * 32 + nt * 8 + tig * 2;
            float bia0 = bias[c0], bia1 = bias[c0 + 1];
#pragma unroll
            for (int half = 0; half < 2; half++) {
                int m = rbase + half * 8;
                if (m >= M) continue;
                float v0 = acc[mt][nt][half * 2 + 0] + bia0;
                float v1 = acc[mt][nt][half * 2 + 1] + bia1;
                if (doRelu) { v0 = fmaxf(v0, 0.f); v1 = fmaxf(v1, 0.f); }
                C[(size_t)m * N + c0] = v0;
                C[(size_t)m * N + c0 + 1] = v1;
            }
        }
    }
}

// -------- cluster labels only: relu + row argmax (warp-per-row) ----------------
__global__ __launch_bounds__(256) void k_cluster(const float* __restrict__ H) {
    int w = blockIdx.x * 8 + (threadIdx.x >> 5);
    int lane = threadIdx.x & 31;
    if (w >= NN) return;
    const float4* Hr = (const float4*)(H + (size_t)w * CC);
    float vmax = -1e30f;
    int vidx = 0x7FFFFFFF;
#pragma unroll
    for (int r = 0; r < 4; r++) {
        float4 v = Hr[r * 32 + lane];
        v.x = fmaxf(v.x, 0.f); v.y = fmaxf(v.y, 0.f);
        v.z = fmaxf(v.z, 0.f); v.w = fmaxf(v.w, 0.f);
        int c0 = (r * 32 + lane) * 4;
        if (v.x > vmax) { vmax = v.x; vidx = c0 + 0; }
        if (v.y > vmax) { vmax = v.y; vidx = c0 + 1; }
        if (v.z > vmax) { vmax = v.z; vidx = c0 + 2; }
        if (v.w > vmax) { vmax = v.w; vidx = c0 + 3; }
    }
#pragma unroll
    for (int off = 16; off > 0; off >>= 1) {
        float om = __shfl_xor_sync(0xFFFFFFFFu, vmax, off);
        int oi = __shfl_xor_sync(0xFFFFFFFFu, vidx, off);
        if (om > vmax || (om == vmax && oi < vidx)) { vmax = om; vidx = oi; }
    }
    if (lane == 0) g_cluster[w] = vidx;
}

// -------- softmax(relu(h3)) S output (warp-per-row, side stream) ---------------
__global__ __launch_bounds__(256) void k_softmaxS(const float* __restrict__ H,
                                                  float* __restrict__ S) {
    int w = blockIdx.x * 8 + (threadIdx.x >> 5);
    int lane = threadIdx.x & 31;
    if (w >= NN) return;
    const float4* Hr = (const float4*)(H + (size_t)w * CC);
    float4 v[4];
    float vmax = -1e30f;
#pragma unroll
    for (int r = 0; r < 4; r++) {
        v[r] = Hr[r * 32 + lane];
        v[r].x = fmaxf(v[r].x, 0.f);
        v[r].y = fmaxf(v[r].y, 0.f);
        v[r].z = fmaxf(v[r].z, 0.f);
        v[r].w = fmaxf(v[r].w, 0.f);
        vmax = fmaxf(vmax, fmaxf(fmaxf(v[r].x, v[r].y), fmaxf(v[r].z, v[r].w)));
    }
#pragma unroll
    for (int off = 16; off > 0; off >>= 1)
        vmax = fmaxf(vmax, __shfl_xor_sync(0xFFFFFFFFu, vmax, off));
    float e[16];
    float sum = 0.0f;
#pragma unroll
    for (int r = 0; r < 4; r++) {
        e[r * 4 + 0] = expf(v[r].x - vmax);
        e[r * 4 + 1] = expf(v[r].y - vmax);
        e[r * 4 + 2] = expf(v[r].z - vmax);
        e[r * 4 + 3] = expf(v[r].w - vmax);
        sum += e[r * 4 + 0] + e[r * 4 + 1] + e[r * 4 + 2] + e[r * 4 + 3];
    }
#pragma unroll
    for (int off = 16; off > 0; off >>= 1) sum += __shfl_xor_sync(0xFFFFFFFFu, sum, off);
    float inv = 1.0f / sum;
    float4* Sr = (float4*)(S + (size_t)w * CC);
#pragma unroll
    for (int r = 0; r < 4; r++)
        Sr[r * 32 + lane] = make_float4(e[r * 4 + 0] * inv, e[r * 4 + 1] * inv,
                                        e[r * 4 + 2] * inv, e[r * 4 + 3] * inv);
}

// ---------------- score layer ------------------------------------------------
__global__ void k_hs(const float* __restrict__ x, const float* __restrict__ Ws) {
    int t = blockIdx.x * blockDim.x + threadIdx.x;
    int w = t >> 5, lane = t & 31;
    if (w >= NN) return;
    float a = 0.0f;
#pragma unroll
    for (int r = 0; r < 4; r++) {
        int f = lane + 32 * r;
        a += x[(size_t)w * FF + f] * Ws[f];
    }
#pragma unroll
    for (int off = 16; off > 0; off >>= 1) a += __shfl_down_sync(0xFFFFFFFFu, a, off);
    if (lane == 0) g_hs[w] = a;
}

__global__ void k_intra() {
    int t = blockIdx.x * blockDim.x + threadIdx.x;
    int i = t >> 5, lane = t & 31;
    if (i >= NN) return;
    int myc = g_cluster[i];
    int beg = g_rowstart[i], end = beg + g_cnt[i];
    int cint = 0;
    for (int j = beg + lane; j < end; j += 32)
        cint += (g_cluster[g_csr[j]] == myc) ? 1 : 0;
#pragma unroll
    for (int off = 16; off > 0; off >>= 1) cint += __shfl_down_sync(0xFFFFFFFFu, cint, off);
    if (lane == 0) {
        float iv = rsqrtf((float)cint + 1.0f);
        g_invs[i] = iv;
        g_ivh[i] = iv * g_hs[i];
        if (cint > 0) atomicOr(&g_nonempty[myc], 1);
    }
}

// score + fused per-cluster (max, first-argmax) 64-bit atomicMax
__global__ void k_score(const float* __restrict__ bs) {
    int t = blockIdx.x * blockDim.x + threadIdx.x;
    int i = t >> 5, lane = t & 31;
    if (i >= NN) return;
    int myc = g_cluster[i];
    int beg = g_rowstart[i], end = beg + g_cnt[i];
    float acc = 0.0f;
    for (int j = beg + lane; j < end; j += 32) {
        int s = g_csr[j];
        if (g_cluster[s] == myc) acc += g_ivh[s];
    }
#pragma unroll
    for (int off = 16; off > 0; off >>= 1) acc += __shfl_down_sync(0xFFFFFFFFu, acc, off);
    if (lane == 0) {
        float invi = g_invs[i];
        float score = tanhf(invi * (acc + g_ivh[i]) + bs[0]);
        unsigned long long key =
            ((unsigned long long)fkey(score) << 32) | (unsigned)(0x7FFFFFFF - i);
        atomicMax(&g_ckey[myc], key);
    }
}

// ---------------- outputs ----------------------------------------------------
__global__ void k_newx(const float* __restrict__ x, float* __restrict__ out) {
    int c = blockIdx.x, f = threadIdx.x;
    float v = 0.0f;
    if (g_nonempty[c]) {
        unsigned long long key = g_ckey[c];
        float alpha = fdec((unsigned)(key >> 32));
        int id = 0x7FFFFFFF - (int)(key & 0xFFFFFFFFull);
        v = x[(size_t)id * FF + f] * alpha;
    }
    out[(size_t)c * FF + f] = v;
}

__global__ void k_zero(float* __restrict__ p, int n) {
    int i = blockIdx.x * blockDim.x + threadIdx.x;
    if (i < n) p[i] = 0.0f;
}

__global__ void k_adj(const int* __restrict__ src, const int* __restrict__ dst,
                      float* __restrict__ adj) {
    int e = blockIdx.x * blockDim.x + threadIdx.x;
    if (e >= EE) return;
    int ci = g_cluster[src[e]], cj = g_cluster[dst[e]];
    if (ci != cj && g_nonempty[ci] && g_nonempty[cj]) adj[ci * CC + cj] = 1.0f;
}

// ---------------- host -------------------------------------------------------
extern "C" void kernel_launch(void* const* d_in, const int* in_sizes, int n_in,
                              void* d_out, int out_size) {
    const float* x  = (const float*)d_in[0];
    const int*   ei = (const int*)d_in[1];
    const int*   src = ei;
    const int*   dst = ei + EE;
    const float* W1 = (const float*)d_in[3];
    const float* b1 = (const float*)d_in[4];
    const float* W2 = (const float*)d_in[5];
    const float* b2 = (const float*)d_in[6];
    const float* W3 = (const float*)d_in[7];
    const float* b3 = (const float*)d_in[8];
    const float* Ws = (const float*)d_in[9];
    const float* bs = (const float*)d_in[10];

    float* out      = (float*)d_out;
    float* out_newx = out;
    float* out_adj  = out + (size_t)CC * FF;
    float* out_S    = out + (size_t)CC * FF + (size_t)CC * CC + CC;

    float *pP, *ph, *ph3, *pWt1, *pWt2, *pWt3;
    cudaGetSymbolAddress((void**)&pP,   g_P);
    cudaGetSymbolAddress((void**)&ph,   g_h);
    cudaGetSymbolAddress((void**)&ph3,  g_h3);
    cudaGetSymbolAddress((void**)&pWt1, g_Wt1);
    cudaGetSymbolAddress((void**)&pWt2, g_Wt2);
    cudaGetSymbolAddress((void**)&pWt3, g_Wt3);

    cudaFuncSetAttribute(k_gemm_fp16, cudaFuncAttributeMaxDynamicSharedMemorySize,
                         GEMM_SMEM_BYTES);

    const int TB = 256;
    int gN = (NN + TB - 1) / TB;
    int gE = (EE + TB - 1) / TB;
    int gW = (NN * 32 + TB - 1) / TB;
    int gP = (NN + 7) / 8;
    int nbScan = (NN + 1023) / 1024;
    int gM = (NN + GBM - 1) / GBM;
    int gR = (NN + 7) / 8;   // warp-per-row kernels

    cudaStream_t s2;
    cudaStreamCreate(&s2);
    cudaEvent_t eFork, eJoin, eH3, eIntra, eS2;
    cudaEventCreateWithFlags(&eFork, cudaEventDisableTiming);
    cudaEventCreateWithFlags(&eJoin, cudaEventDisableTiming);
    cudaEventCreateWithFlags(&eH3,   cudaEventDisableTiming);
    cudaEventCreateWithFlags(&eIntra, cudaEventDisableTiming);
    cudaEventCreateWithFlags(&eS2,   cudaEventDisableTiming);

    // --- fork side stream: output zeroing + weight transposes + k_hs, all
    // --- independent of the CSR build on the main stream.
    cudaEventRecord(eFork, 0);
    cudaStreamWaitEvent(s2, eFork, 0);
    dim3 tb(32, 8);
    int zn = CC * CC + CC;   // adjacency + new_batch region
    k_zero<<<(zn + TB - 1) / TB, TB, 0, s2>>>(out_adj, zn);
    k_transW<<<dim3(HH / 32, FF / 32), tb, 0, s2>>>(W1, pWt1, FF, HH);
    k_transW<<<dim3(HH / 32, HH / 32), tb, 0, s2>>>(W2, pWt2, HH, HH);
    k_transW<<<dim3(CC / 32, HH / 32), tb, 0, s2>>>(W3, pWt3, HH, CC);
    k_hs<<<gW, TB, 0, s2>>>(x, Ws);
    cudaEventRecord(eJoin, s2);

    // graph build (CSR) + degree normalization (main stream)
    k_init<<<gN, TB>>>();
    k_count<<<gE, TB>>>(dst);
    k_scan1<<<nbScan, 1024>>>();
    k_scan3<<<gN, TB>>>(nbScan);
    k_scatter<<<gE, TB>>>(src, dst);

    // 3-layer GCN: propagate (input space) -> fp16x3 tensor-core linear
    k_prop<FF><<<gP, TB>>>(x, pP);
    cudaStreamWaitEvent(0, eJoin, 0);   // weights + hs ready
    k_gemm_fp16<<<dim3(HH / GBN, gM), 512, GEMM_SMEM_BYTES>>>(pP, pWt1, b1, ph, NN, HH, FF, 1);
    k_prop<HH><<<gP, TB>>>(ph, pP);
    k_gemm_fp16<<<dim3(HH / GBN, gM), 512, GEMM_SMEM_BYTES>>>(pP, pWt2, b2, ph, NN, HH, HH, 1);
    k_prop<HH><<<gP, TB>>>(ph, pP);
    k_gemm_fp16<<<dim3(CC / GBN, gM), 512, GEMM_SMEM_BYTES>>>(pP, pWt3, b3, ph3, NN, CC, HH, 0);
    cudaEventRecord(eH3, 0);

    // main stream: cluster labels -> intra -> score -> newx (critical path)
    k_cluster<<<gR, TB>>>(ph3);
    k_intra<<<gW, TB>>>();
    cudaEventRecord(eIntra, 0);
    k_score<<<gW, TB>>>(bs);
    k_newx<<<CC, FF>>>(x, out_newx);

    // side stream: S softmax (off critical path) then adjacency
    cudaStreamWaitEvent(s2, eH3, 0);
    k_softmaxS<<<gR, TB, 0, s2>>>(ph3, out_S);
    cudaStreamWaitEvent(s2, eIntra, 0);
    k_adj<<<gE, TB, 0, s2>>>(src, dst, out_adj);
    cudaEventRecord(eS2, s2);

    // join everything back to the origin stream
    cudaStreamWaitEvent(0, eS2, 0);
}